// round 14
// baseline (speedup 1.0000x reference)
#include <cuda_runtime.h>
#include <cuda_fp16.h>
#include <cstdint>

#define N_NODES 50000
#define N_EDGES 800000
#define D 128
#define N_CLS 47

#define SCAN_CHUNK 512
#define SCAN_BLOCKS ((N_NODES + SCAN_CHUNK - 1) / SCAN_CHUNK)  // 98

// ---------------- scratch (no allocations allowed) ----------------
__device__ int   g_deg[N_NODES];
__device__ int   g_row_ptr[N_NODES + 1];
__device__ int   g_rank[N_EDGES];
__device__ int   g_csr_src[N_EDGES];
__device__ float g_inv_deg[N_NODES];
__device__ int   g_blk_sum[SCAN_BLOCKS];
__device__ int   g_blk_off[SCAN_BLOCKS];
__device__ int   g_arrive;
__device__ volatile int g_flag;

__device__ __half g_f[N_NODES * D];
__device__ __half g_h1[N_NODES * D];
__device__ __half g_h2[N_NODES * D];
__device__ __half g_agg[N_NODES * D];   // also reused as y (50000 x 48) in layer 2

// Weights pre-transposed. B0/B1: [n][k], k in [0,256). B2: [n][k], n in [0,96), k in [0,128)
__device__ __half g_B0[128 * 256];
__device__ __half g_B1[128 * 256];
__device__ __half g_B2[96 * 128];

// ---------------- PTX helpers (baseline PTX only) ----------------
__device__ __forceinline__ uint32_t s2u(const void* p) {
    uint32_t a;
    asm("{ .reg .u64 t; cvta.to.shared.u64 t, %1; cvt.u32.u64 %0, t; }" : "=r"(a) : "l"(p));
    return a;
}

__device__ __forceinline__ void ldsm_x4(uint32_t& r0, uint32_t& r1, uint32_t& r2, uint32_t& r3,
                                        uint32_t addr) {
    asm volatile("ldmatrix.sync.aligned.m8n8.x4.shared.b16 {%0,%1,%2,%3}, [%4];"
                 : "=r"(r0), "=r"(r1), "=r"(r2), "=r"(r3) : "r"(addr));
}

__device__ __forceinline__ void mma_f16(float* c, const uint32_t* a, const uint32_t* b) {
    asm volatile(
        "mma.sync.aligned.m16n8k16.row.col.f32.f16.f16.f32 "
        "{%0,%1,%2,%3}, {%4,%5,%6,%7}, {%8,%9}, {%0,%1,%2,%3};"
        : "+f"(c[0]), "+f"(c[1]), "+f"(c[2]), "+f"(c[3])
        : "r"(a[0]), "r"(a[1]), "r"(a[2]), "r"(a[3]), "r"(b[0]), "r"(b[1]));
}

// ---------------- CSR build ----------------
__global__ void count_rank_kernel(const int* __restrict__ dst) {
    if (blockIdx.x == 0 && threadIdx.x == 0) { g_arrive = 0; g_flag = 0; }
    int t = blockIdx.x * blockDim.x + threadIdx.x;
    int e = t * 2;
    if (e + 1 < N_EDGES) {
        int2 dd = *(const int2*)&dst[e];
        int r0 = atomicAdd(&g_deg[dd.x], 1);
        int r1 = atomicAdd(&g_deg[dd.y], 1);
        *(int2*)&g_rank[e] = make_int2(r0, r1);
    } else if (e < N_EDGES) {
        g_rank[e] = atomicAdd(&g_deg[dst[e]], 1);
    }
}

__global__ void scan_fused_kernel() {
    __shared__ int wsum[16];
    __shared__ int sh_is_last;
    int tid = threadIdx.x;
    int lane = tid & 31;
    int w = tid >> 5;
    int b = blockIdx.x;
    int i = b * SCAN_CHUNK + tid;
    int d = (i < N_NODES) ? g_deg[i] : 0;

    int v = d;
#pragma unroll
    for (int off = 1; off < 32; off <<= 1) {
        int t = __shfl_up_sync(0xffffffffu, v, off);
        if (lane >= off) v += t;
    }
    if (lane == 31) wsum[w] = v;
    __syncthreads();
    if (w == 0) {
        int x = (lane < 16) ? wsum[lane] : 0;
#pragma unroll
        for (int off = 1; off < 16; off <<= 1) {
            int t = __shfl_up_sync(0xffffffffu, x, off);
            if (lane >= off) x += t;
        }
        if (lane < 16) wsum[lane] = x;
    }
    __syncthreads();
    int incl = v + ((w > 0) ? wsum[w - 1] : 0);
    int blocksum = wsum[15];

    if (tid == 0) {
        g_blk_sum[b] = blocksum;
        __threadfence();
        int t = atomicAdd(&g_arrive, 1);
        sh_is_last = (t == SCAN_BLOCKS - 1) ? 1 : 0;
    }
    __syncthreads();

    if (sh_is_last && w == 0) {
        int base = lane * 4;
        int s[4];
        int tot = 0;
#pragma unroll
        for (int j = 0; j < 4; j++) {
            s[j] = (base + j < SCAN_BLOCKS) ? g_blk_sum[base + j] : 0;
            tot += s[j];
        }
        int ex = tot;
#pragma unroll
        for (int off = 1; off < 32; off <<= 1) {
            int t = __shfl_up_sync(0xffffffffu, ex, off);
            if (lane >= off) ex += t;
        }
        ex -= tot;
        int run = ex;
#pragma unroll
        for (int j = 0; j < 4; j++) {
            if (base + j < SCAN_BLOCKS) g_blk_off[base + j] = run;
            run += s[j];
        }
        if (lane == 0) g_row_ptr[N_NODES] = N_EDGES;
        __threadfence();
        __syncwarp();
        if (lane == 0) g_flag = 1;
    }

    if (tid == 0) {
        while (g_flag == 0) { __nanosleep(256); }
    }
    __syncthreads();

    if (i < N_NODES) {
        int excl = g_blk_off[b] + incl - d;
        g_row_ptr[i] = excl;
        g_inv_deg[i] = 1.0f / (float)(d > 1 ? d : 1);
    }
}

__global__ void fill_csr_kernel(const int* __restrict__ src, const int* __restrict__ dst) {
    int t = blockIdx.x * blockDim.x + threadIdx.x;
    int e = t * 2;
    if (e + 1 < N_EDGES) {
        int2 dd = *(const int2*)&dst[e];
        int2 rr = *(const int2*)&g_rank[e];
        int2 ss = *(const int2*)&src[e];
        g_csr_src[__ldg(&g_row_ptr[dd.x]) + rr.x] = ss.x;
        g_csr_src[__ldg(&g_row_ptr[dd.y]) + rr.y] = ss.y;
    } else if (e < N_EDGES) {
        g_csr_src[__ldg(&g_row_ptr[dst[e]]) + g_rank[e]] = src[e];
    }
}

// ---------------- weight prep ----------------
__global__ void prep_all_kernel(const float* __restrict__ Ws0, const float* __restrict__ Wn0,
                                const float* __restrict__ Ws1, const float* __restrict__ Wn1,
                                const float* __restrict__ Ws2, const float* __restrict__ Wn2) {
    int layer = blockIdx.y;
    int i = blockIdx.x * blockDim.x + threadIdx.x;
    if (layer < 2) {
        const float* Ws = (layer == 0) ? Ws0 : Ws1;
        const float* Wn = (layer == 0) ? Wn0 : Wn1;
        __half* B = (layer == 0) ? g_B0 : g_B1;
        if (i >= 128 * 256) return;
        int n = i / 256, k = i % 256;
        float w = (k < 128) ? Ws[k * 128 + n] : Wn[(k - 128) * 128 + n];
        B[i] = __float2half_rn(w);
    } else {
        // B2: [96][128]; n<48 -> Ws2 col n (47 real), n>=48 -> Wn2 col n-48 (47 real)
        if (i >= 96 * 128) return;
        int n = i / 128, k = i % 128;
        float w = 0.0f;
        if (n < 48) { if (n < 47) w = Ws2[k * 47 + n]; }
        else { if (n - 48 < 47) w = Wn2[k * 47 + (n - 48)]; }
        g_B2[i] = __float2half_rn(w);
    }
}

// ---------------- fp32 -> fp16 (features) ----------------
__global__ void convert_kernel(const float* __restrict__ x, __half* __restrict__ o, int n) {
    int i = blockIdx.x * blockDim.x + threadIdx.x;
    if (i >= n) return;
    o[i] = __float2half_rn(x[i]);
}

// ---------------- mean aggregation over fp16 128-dim rows: one warp per node ----------------
__global__ void agg_kernel(const __half* __restrict__ hsrc) {
    int warp = (blockIdx.x * blockDim.x + threadIdx.x) >> 5;
    int lane = threadIdx.x & 31;
    if (warp >= N_NODES) return;
    int beg = g_row_ptr[warp];
    int end = g_row_ptr[warp + 1];
    float a0 = 0.f, a1 = 0.f, a2 = 0.f, a3 = 0.f;
    int e = beg;
    for (; e + 4 <= end; e += 4) {
        int u0 = __ldg(&g_csr_src[e]);
        int u1 = __ldg(&g_csr_src[e + 1]);
        int u2 = __ldg(&g_csr_src[e + 2]);
        int u3 = __ldg(&g_csr_src[e + 3]);
        uint2 v0 = __ldg((const uint2*)&hsrc[(long)u0 * D + lane * 4]);
        uint2 v1 = __ldg((const uint2*)&hsrc[(long)u1 * D + lane * 4]);
        uint2 v2 = __ldg((const uint2*)&hsrc[(long)u2 * D + lane * 4]);
        uint2 v3 = __ldg((const uint2*)&hsrc[(long)u3 * D + lane * 4]);
#pragma unroll
        for (int j = 0; j < 4; j++) {
            uint2 v = (j == 0) ? v0 : (j == 1) ? v1 : (j == 2) ? v2 : v3;
            float2 p0 = __half22float2(*(__half2*)&v.x);
            float2 p1 = __half22float2(*(__half2*)&v.y);
            a0 += p0.x; a1 += p0.y; a2 += p1.x; a3 += p1.y;
        }
    }
    for (; e < end; e++) {
        int u = __ldg(&g_csr_src[e]);
        uint2 v = __ldg((const uint2*)&hsrc[(long)u * D + lane * 4]);
        float2 p0 = __half22float2(*(__half2*)&v.x);
        float2 p1 = __half22float2(*(__half2*)&v.y);
        a0 += p0.x; a1 += p0.y; a2 += p1.x; a3 += p1.y;
    }
    float s = g_inv_deg[warp];
    __half2 o01 = __floats2half2_rn(a0 * s, a1 * s);
    __half2 o23 = __floats2half2_rn(a2 * s, a3 * s);
    long off = (long)warp * D + lane * 4;
    *(uint2*)&g_agg[off] = make_uint2(*(uint32_t*)&o01, *(uint32_t*)&o23);
}

// ---------------- fp16 HMMA persistent dual GEMM (layers 0/1) ----------------
template <int NOUT>
__global__ void __launch_bounds__(256, 2) gemm_mma(
    const __half* __restrict__ x,
    const __half* __restrict__ Bg,
    const float* __restrict__ bias,
    __half* __restrict__ o_h, int ntiles) {
    constexpr int KS_B = 264;
    constexpr int KS_A = 136;
    constexpr int MT = 2;
    constexpr int NT = 8;
    constexpr int NP = NT / 2;

    extern __shared__ __half sm[];
    __half* sB = sm;                   // NOUT x 264
    __half* sA = sB + NOUT * KS_B;     // 128 x 136
    float* sbias = (float*)(sA + 128 * KS_A);

    int tid = threadIdx.x;
    int wid = tid >> 5;
    int lane = tid & 31;

    int warpM = (wid & 3) * 32;
    int warpN = (wid >> 2) * 64;

    for (int i = tid; i < NOUT * 32; i += 256) {
        int n = i >> 5;
        int k8 = (i & 31) << 3;
        *(uint4*)&sB[n * KS_B + k8] = *(const uint4*)&Bg[n * 256 + k8];
    }
    if (tid < NOUT) sbias[tid] = bias[tid];

    uint32_t uA = s2u(sA), uB = s2u(sB);

    int g = lane >> 3;
    int rA = (g & 1) * 8 + (lane & 7);
    int kA = (g >> 1) * 8;
    int rB4 = (g >> 1) * 8 + (lane & 7);
    int kB4 = (g & 1) * 8;

    int qr = lane >> 2;
    int qc = (lane & 3) * 2;

    for (int tile = blockIdx.x; tile < ntiles; tile += gridDim.x) {
        int m0 = tile * 128;

        float acc[MT][NT][4];
#pragma unroll
        for (int mt = 0; mt < MT; mt++)
#pragma unroll
            for (int nt = 0; nt < NT; nt++)
#pragma unroll
                for (int j = 0; j < 4; j++) acc[mt][nt][j] = 0.0f;

#pragma unroll 1
        for (int c = 0; c < 2; c++) {
            const __half* srcA = (c == 0) ? x : g_agg;
            __syncthreads();
            for (int i = tid; i < 128 * 16; i += 256) {
                int r = i >> 4;
                int k8 = (i & 15) << 3;
                int m = m0 + r;
                uint4 v = make_uint4(0, 0, 0, 0);
                if (m < N_NODES) v = *(const uint4*)&srcA[(long)m * 128 + k8];
                *(uint4*)&sA[r * KS_A + k8] = v;
            }
            __syncthreads();

#pragma unroll
            for (int kk = 0; kk < 128; kk += 16) {
                uint32_t a[MT][4];
#pragma unroll
                for (int mt = 0; mt < MT; mt++) {
                    uint32_t off = (uint32_t)((warpM + mt * 16 + rA) * KS_A + kk + kA) * 2;
                    ldsm_x4(a[mt][0], a[mt][1], a[mt][2], a[mt][3], uA + off);
                }
                uint32_t b[NT][2];
#pragma unroll
                for (int p = 0; p < NP; p++) {
                    uint32_t off =
                        (uint32_t)((warpN + p * 16 + rB4) * KS_B + c * 128 + kk + kB4) * 2;
                    ldsm_x4(b[2 * p][0], b[2 * p][1], b[2 * p + 1][0], b[2 * p + 1][1], uB + off);
                }
#pragma unroll
                for (int mt = 0; mt < MT; mt++)
#pragma unroll
                    for (int nt = 0; nt < NT; nt++) mma_f16(acc[mt][nt], a[mt], b[nt]);
            }
        }

#pragma unroll
        for (int mt = 0; mt < MT; mt++) {
#pragma unroll
            for (int nt = 0; nt < NT; nt++) {
                int n = warpN + nt * 8 + qc;
                float bn0 = sbias[n], bn1 = sbias[n + 1];
#pragma unroll
                for (int half = 0; half < 2; half++) {
                    int m = m0 + warpM + mt * 16 + qr + half * 8;
                    if (m >= N_NODES) continue;
                    float v0 = fmaxf(acc[mt][nt][half * 2 + 0] + bn0, 0.0f);
                    float v1 = fmaxf(acc[mt][nt][half * 2 + 1] + bn1, 0.0f);
                    __half2 hv = __floats2half2_rn(v0, v1);
                    *(uint32_t*)&o_h[(long)m * 128 + n] = *(uint32_t*)&hv;
                }
            }
        }
    }
}

// ---------------- layer-2 GEMM: Z[128,96] = h2 @ [Ws2|Wn2]; self->out fp32, y->g_agg fp16 ----------------
__global__ void __launch_bounds__(256, 2) gemm_l2(
    const __half* __restrict__ x,
    const float* __restrict__ bias,
    float* __restrict__ out,
    __half* __restrict__ y, int ntiles) {
    constexpr int KS_B = 136;  // K=128 + 8 pad
    constexpr int KS_A = 136;
    constexpr int NT = 12;     // 96 cols
    constexpr int NP = 6;

    extern __shared__ __half sm[];
    __half* sB = sm;                   // 96 x 136
    __half* sA = sB + 96 * KS_B;       // 128 x 136
    float* sbias = (float*)(sA + 128 * KS_A);

    int tid = threadIdx.x;
    int wid = tid >> 5;
    int lane = tid & 31;

    int warpM = wid * 16;  // 8 warps x 16 rows = 128

    for (int i = tid; i < 96 * 16; i += 256) {
        int n = i >> 4;
        int k8 = (i & 15) << 3;
        *(uint4*)&sB[n * KS_B + k8] = *(const uint4*)&g_B2[n * 128 + k8];
    }
    if (tid < 48) sbias[tid] = (tid < N_CLS) ? bias[tid] : 0.0f;

    uint32_t uA = s2u(sA), uB = s2u(sB);

    int g = lane >> 3;
    int rA = (g & 1) * 8 + (lane & 7);
    int kA = (g >> 1) * 8;
    int rB4 = (g >> 1) * 8 + (lane & 7);
    int kB4 = (g & 1) * 8;

    int qr = lane >> 2;
    int qc = (lane & 3) * 2;

    for (int tile = blockIdx.x; tile < ntiles; tile += gridDim.x) {
        int m0 = tile * 128;

        float acc[NT][4];
#pragma unroll
        for (int nt = 0; nt < NT; nt++)
#pragma unroll
            for (int j = 0; j < 4; j++) acc[nt][j] = 0.0f;

        __syncthreads();
        for (int i = tid; i < 128 * 16; i += 256) {
            int r = i >> 4;
            int k8 = (i & 15) << 3;
            int m = m0 + r;
            uint4 v = make_uint4(0, 0, 0, 0);
            if (m < N_NODES) v = *(const uint4*)&x[(long)m * 128 + k8];
            *(uint4*)&sA[r * KS_A + k8] = v;
        }
        __syncthreads();

#pragma unroll
        for (int kk = 0; kk < 128; kk += 16) {
            uint32_t a[4];
            {
                uint32_t off = (uint32_t)((warpM + rA) * KS_A + kk + kA) * 2;
                ldsm_x4(a[0], a[1], a[2], a[3], uA + off);
            }
            uint32_t b[NT][2];
#pragma unroll
            for (int p = 0; p < NP; p++) {
                uint32_t off = (uint32_t)((p * 16 + rB4) * KS_B + kk + kB4) * 2;
                ldsm_x4(b[2 * p][0], b[2 * p][1], b[2 * p + 1][0], b[2 * p + 1][1], uB + off);
            }
#pragma unroll
            for (int nt = 0; nt < NT; nt++) mma_f16(acc[nt], a, b[nt]);
        }

#pragma unroll
        for (int nt = 0; nt < NT; nt++) {
            int n = nt * 8 + qc;
#pragma unroll
            for (int half = 0; half < 2; half++) {
                int m = m0 + warpM + qr + half * 8;
                if (m >= N_NODES) continue;
                float v0 = acc[nt][half * 2 + 0];
                float v1 = acc[nt][half * 2 + 1];
                if (n < 48) {
                    // self part + bias -> out fp32
                    if (n < N_CLS) out[(long)m * N_CLS + n] = v0 + sbias[n];
                    if (n + 1 < 48 && n + 1 < N_CLS) out[(long)m * N_CLS + n + 1] = v1 + sbias[n + 1];
                } else {
                    // y part -> fp16 (48-col stride; pad col 47 is zero weights)
                    __half2 hv = __floats2half2_rn(v0, v1);
                    *(uint32_t*)&y[(long)m * 48 + (n - 48)] = *(uint32_t*)&hv;
                }
            }
        }
    }
}

// ---------------- final: out[v] += mean_{u->v} y[u]  (47 cols) ----------------
__global__ void agg_out_kernel(const __half* __restrict__ y, float* __restrict__ out) {
    int node = (blockIdx.x * blockDim.x + threadIdx.x) >> 5;
    int lane = threadIdx.x & 31;
    if (node >= N_NODES) return;
    int beg = g_row_ptr[node];
    int end = g_row_ptr[node + 1];
    // lanes 0..23 each own 2 cols (half2); lane 23 owns cols 46,47 (47 = pad)
    bool act = lane < 24;
    float a0 = 0.f, a1 = 0.f;
    int e = beg;
    for (; e + 4 <= end; e += 4) {
        int u0 = __ldg(&g_csr_src[e]);
        int u1 = __ldg(&g_csr_src[e + 1]);
        int u2 = __ldg(&g_csr_src[e + 2]);
        int u3 = __ldg(&g_csr_src[e + 3]);
        if (act) {
            uint32_t w0 = __ldg((const uint32_t*)&y[(long)u0 * 48 + lane * 2]);
            uint32_t w1 = __ldg((const uint32_t*)&y[(long)u1 * 48 + lane * 2]);
            uint32_t w2 = __ldg((const uint32_t*)&y[(long)u2 * 48 + lane * 2]);
            uint32_t w3 = __ldg((const uint32_t*)&y[(long)u3 * 48 + lane * 2]);
#pragma unroll
            for (int j = 0; j < 4; j++) {
                uint32_t w = (j == 0) ? w0 : (j == 1) ? w1 : (j == 2) ? w2 : w3;
                float2 pv = __half22float2(*(__half2*)&w);
                a0 += pv.x; a1 += pv.y;
            }
        }
    }
    for (; e < end; e++) {
        int u = __ldg(&g_csr_src[e]);
        if (act) {
            uint32_t w = __ldg((const uint32_t*)&y[(long)u * 48 + lane * 2]);
            float2 pv = __half22float2(*(__half2*)&w);
            a0 += pv.x; a1 += pv.y;
        }
    }
    if (act) {
        float s = g_inv_deg[node];
        int c = lane * 2;
        long base = (long)node * N_CLS;
        out[base + c] += a0 * s;
        if (c + 1 < N_CLS) out[base + c + 1] += a1 * s;
    }
}

// ---------------- launch ----------------
extern "C" void kernel_launch(void* const* d_in, const int* in_sizes, int n_in,
                              void* d_out, int out_size) {
    const float* features = (const float*)d_in[0];
    const int*   src      = (const int*)d_in[1];
    const int*   dst      = (const int*)d_in[2];
    const float* Ws0 = (const float*)d_in[3];
    const float* Wn0 = (const float*)d_in[4];
    const float* b0  = (const float*)d_in[5];
    const float* Ws1 = (const float*)d_in[6];
    const float* Wn1 = (const float*)d_in[7];
    const float* b1  = (const float*)d_in[8];
    const float* Ws2 = (const float*)d_in[9];
    const float* Wn2 = (const float*)d_in[10];
    const float* b2  = (const float*)d_in[11];
    float* out = (float*)d_out;

    void* p;
    cudaGetSymbolAddress(&p, g_f);   __half* f = (__half*)p;
    cudaGetSymbolAddress(&p, g_h1);  __half* h1 = (__half*)p;
    cudaGetSymbolAddress(&p, g_h2);  __half* h2 = (__half*)p;
    cudaGetSymbolAddress(&p, g_agg); __half* yv = (__half*)p;
    cudaGetSymbolAddress(&p, g_B0);  __half* B0 = (__half*)p;
    cudaGetSymbolAddress(&p, g_B1);  __half* B1 = (__half*)p;
    void* degp; cudaGetSymbolAddress(&degp, g_deg);

    const int SMEM128 = (128 * 264 + 128 * 136) * 2 + 512;   // 102,912
    const int SMEM_L2 = (96 * 136 + 128 * 136) * 2 + 512;    //  61,440
    cudaFuncSetAttribute(gemm_mma<128>,
                         cudaFuncAttributeMaxDynamicSharedMemorySize, SMEM128);
    cudaFuncSetAttribute(gemm_l2,
                         cudaFuncAttributeMaxDynamicSharedMemorySize, SMEM_L2);

    // Fork: CSR chain on main stream, weight-prep + feature-convert on s2.
    cudaStream_t s2;
    cudaStreamCreateWithFlags(&s2, cudaStreamNonBlocking);
    cudaEvent_t e_fork, e_join;
    cudaEventCreateWithFlags(&e_fork, cudaEventDisableTiming);
    cudaEventCreateWithFlags(&e_join, cudaEventDisableTiming);

    cudaEventRecord(e_fork, 0);
    cudaStreamWaitEvent(s2, e_fork, 0);

    // s2: prep + convert
    prep_all_kernel<<<dim3(128, 3), 256, 0, s2>>>(Ws0, Wn0, Ws1, Wn1, Ws2, Wn2);
    convert_kernel<<<(N_NODES * D + 255) / 256, 256, 0, s2>>>(features, f, N_NODES * D);
    cudaEventRecord(e_join, s2);

    // main: CSR build
    cudaMemsetAsync(degp, 0, N_NODES * sizeof(int));
    const int EDGE2_BLOCKS = ((N_EDGES + 1) / 2 + 255) / 256;
    count_rank_kernel<<<EDGE2_BLOCKS, 256>>>(dst);
    scan_fused_kernel<<<SCAN_BLOCKS, SCAN_CHUNK>>>();
    fill_csr_kernel<<<EDGE2_BLOCKS, 256>>>(src, dst);

    cudaStreamWaitEvent(0, e_join, 0);

    const int AGG_BLOCKS = (N_NODES * 32 + 255) / 256;
    const int NTILES = (N_NODES + 127) / 128;  // 391
    const int GEMM_GRID = 296;

    // Layer 0
    agg_kernel<<<AGG_BLOCKS, 256>>>(f);
    gemm_mma<128><<<GEMM_GRID, 256, SMEM128>>>(f, B0, b0, h1, NTILES);

    // Layer 1
    agg_kernel<<<AGG_BLOCKS, 256>>>(h1);
    gemm_mma<128><<<GEMM_GRID, 256, SMEM128>>>(h1, B1, b1, h2, NTILES);

    // Layer 2: transform first (self->out, y=h2@Wn2), then aggregate y into out
    gemm_l2<<<GEMM_GRID, 256, SMEM_L2>>>(h2, b2, out, yv, NTILES);
    agg_out_kernel<<<AGG_BLOCKS, 256>>>(yv, out);
}

// round 15
// speedup vs baseline: 1.0613x; 1.0613x over previous
#include <cuda_runtime.h>
#include <cuda_fp16.h>
#include <cstdint>

#define N_NODES 50000
#define N_EDGES 800000
#define D 128
#define N_CLS 47

#define SCAN_CHUNK 512
#define SCAN_BLOCKS ((N_NODES + SCAN_CHUNK - 1) / SCAN_CHUNK)  // 98

// ---------------- scratch (no allocations allowed; zero-initialized at load) ----------------
__device__ int   g_deg[N_NODES];
__device__ int   g_row_ptr[N_NODES + 1];
__device__ int   g_rank[N_EDGES];
__device__ int   g_csr_src[N_EDGES];
__device__ float g_inv_deg[N_NODES];
__device__ int   g_blk_sum[SCAN_BLOCKS];
__device__ int   g_blk_off[SCAN_BLOCKS];
__device__ int   g_arrive;
__device__ volatile int g_flag;

__device__ __half g_f[N_NODES * D];
__device__ __half g_h1[N_NODES * D];
__device__ __half g_h2[N_NODES * D];
__device__ __half g_agg[N_NODES * D];

// Weights pre-transposed + K-concatenated: B[n][k], k in [0,256), fp16
__device__ __half g_B0[128 * 256];
__device__ __half g_B1[128 * 256];
__device__ __half g_B2[48 * 256];

// ---------------- PTX helpers (baseline PTX only) ----------------
__device__ __forceinline__ uint32_t s2u(const void* p) {
    uint32_t a;
    asm("{ .reg .u64 t; cvta.to.shared.u64 t, %1; cvt.u32.u64 %0, t; }" : "=r"(a) : "l"(p));
    return a;
}

__device__ __forceinline__ void ldsm_x4(uint32_t& r0, uint32_t& r1, uint32_t& r2, uint32_t& r3,
                                        uint32_t addr) {
    asm volatile("ldmatrix.sync.aligned.m8n8.x4.shared.b16 {%0,%1,%2,%3}, [%4];"
                 : "=r"(r0), "=r"(r1), "=r"(r2), "=r"(r3) : "r"(addr));
}

__device__ __forceinline__ void mma_f16(float* c, const uint32_t* a, const uint32_t* b) {
    asm volatile(
        "mma.sync.aligned.m16n8k16.row.col.f32.f16.f16.f32 "
        "{%0,%1,%2,%3}, {%4,%5,%6,%7}, {%8,%9}, {%0,%1,%2,%3};"
        : "+f"(c[0]), "+f"(c[1]), "+f"(c[2]), "+f"(c[3])
        : "r"(a[0]), "r"(a[1]), "r"(a[2]), "r"(a[3]), "r"(b[0]), "r"(b[1]));
}

// ---------------- CSR build ----------------
// g_deg enters zeroed (load-time zero-init on call 1, scan-tail zeroing on replays).
__global__ void count_rank_kernel(const int* __restrict__ dst) {
    if (blockIdx.x == 0 && threadIdx.x == 0) { g_arrive = 0; g_flag = 0; }
    int t = blockIdx.x * blockDim.x + threadIdx.x;
    int e = t * 2;
    if (e + 1 < N_EDGES) {
        int2 dd = *(const int2*)&dst[e];
        int r0 = atomicAdd(&g_deg[dd.x], 1);
        int r1 = atomicAdd(&g_deg[dd.y], 1);
        *(int2*)&g_rank[e] = make_int2(r0, r1);
    } else if (e < N_EDGES) {
        g_rank[e] = atomicAdd(&g_deg[dst[e]], 1);
    }
}

// Shuffle-based fused scan with nanosleep-backoff spin.
// Tail also zeroes this block's g_deg chunk for the next graph replay.
__global__ void scan_fused_kernel() {
    __shared__ int wsum[16];
    __shared__ int sh_is_last;
    int tid = threadIdx.x;
    int lane = tid & 31;
    int w = tid >> 5;
    int b = blockIdx.x;
    int i = b * SCAN_CHUNK + tid;
    int d = (i < N_NODES) ? g_deg[i] : 0;

    int v = d;
#pragma unroll
    for (int off = 1; off < 32; off <<= 1) {
        int t = __shfl_up_sync(0xffffffffu, v, off);
        if (lane >= off) v += t;
    }
    if (lane == 31) wsum[w] = v;
    __syncthreads();
    if (w == 0) {
        int x = (lane < 16) ? wsum[lane] : 0;
#pragma unroll
        for (int off = 1; off < 16; off <<= 1) {
            int t = __shfl_up_sync(0xffffffffu, x, off);
            if (lane >= off) x += t;
        }
        if (lane < 16) wsum[lane] = x;
    }
    __syncthreads();
    int incl = v + ((w > 0) ? wsum[w - 1] : 0);
    int blocksum = wsum[15];

    if (tid == 0) {
        g_blk_sum[b] = blocksum;
        __threadfence();
        int t = atomicAdd(&g_arrive, 1);
        sh_is_last = (t == SCAN_BLOCKS - 1) ? 1 : 0;
    }
    __syncthreads();

    if (sh_is_last && w == 0) {
        int base = lane * 4;
        int s[4];
        int tot = 0;
#pragma unroll
        for (int j = 0; j < 4; j++) {
            s[j] = (base + j < SCAN_BLOCKS) ? g_blk_sum[base + j] : 0;
            tot += s[j];
        }
        int ex = tot;
#pragma unroll
        for (int off = 1; off < 32; off <<= 1) {
            int t = __shfl_up_sync(0xffffffffu, ex, off);
            if (lane >= off) ex += t;
        }
        ex -= tot;
        int run = ex;
#pragma unroll
        for (int j = 0; j < 4; j++) {
            if (base + j < SCAN_BLOCKS) g_blk_off[base + j] = run;
            run += s[j];
        }
        if (lane == 0) g_row_ptr[N_NODES] = N_EDGES;
        __threadfence();
        __syncwarp();
        if (lane == 0) g_flag = 1;
    }

    if (tid == 0) {
        while (g_flag == 0) { __nanosleep(256); }
    }
    __syncthreads();

    if (i < N_NODES) {
        int excl = g_blk_off[b] + incl - d;
        g_row_ptr[i] = excl;
        g_inv_deg[i] = 1.0f / (float)(d > 1 ? d : 1);
        g_deg[i] = 0;   // ready for next replay (only this block reads this chunk)
    }
}

// Atomic-free fill, 2 edges per thread.
__global__ void fill_csr_kernel(const int* __restrict__ src, const int* __restrict__ dst) {
    int t = blockIdx.x * blockDim.x + threadIdx.x;
    int e = t * 2;
    if (e + 1 < N_EDGES) {
        int2 dd = *(const int2*)&dst[e];
        int2 rr = *(const int2*)&g_rank[e];
        int2 ss = *(const int2*)&src[e];
        g_csr_src[__ldg(&g_row_ptr[dd.x]) + rr.x] = ss.x;
        g_csr_src[__ldg(&g_row_ptr[dd.y]) + rr.y] = ss.y;
    } else if (e < N_EDGES) {
        g_csr_src[__ldg(&g_row_ptr[dst[e]]) + g_rank[e]] = src[e];
    }
}

// ---------------- fused weight prep (3 layers) + feature fp32->fp16 convert ----------------
// blocks [0, CONV_BLOCKS): convert;  [CONV_BLOCKS, +128): B0;  next 128: B1;  next 48: B2
#define CONV_BLOCKS ((N_NODES * D + 255) / 256)   // 25000
__global__ void prep_convert_kernel(const float* __restrict__ x, __half* __restrict__ o,
                                    const float* __restrict__ Ws0, const float* __restrict__ Wn0,
                                    const float* __restrict__ Ws1, const float* __restrict__ Wn1,
                                    const float* __restrict__ Ws2, const float* __restrict__ Wn2) {
    int bid = blockIdx.x;
    if (bid < CONV_BLOCKS) {
        int i = bid * blockDim.x + threadIdx.x;
        if (i < N_NODES * D) o[i] = __float2half_rn(x[i]);
        return;
    }
    int pb = bid - CONV_BLOCKS;
    const float* Ws;
    const float* Wn;
    __half* B;
    int nreal, npad;
    if (pb < 128) { Ws = Ws0; Wn = Wn0; B = g_B0; nreal = 128; npad = 128; }
    else if (pb < 256) { pb -= 128; Ws = Ws1; Wn = Wn1; B = g_B1; nreal = 128; npad = 128; }
    else { pb -= 256; Ws = Ws2; Wn = Wn2; B = g_B2; nreal = 47; npad = 48; }
    int i = pb * blockDim.x + threadIdx.x;
    if (i >= npad * 256) return;
    int n = i / 256, k = i % 256;
    float w = 0.0f;
    if (n < nreal) w = (k < 128) ? Ws[k * nreal + n] : Wn[(k - 128) * nreal + n];
    B[i] = __float2half_rn(w);
}

// ---------------- mean aggregation over fp16 rows: one warp per node ----------------
__global__ void agg_kernel(const __half* __restrict__ hsrc) {
    int warp = (blockIdx.x * blockDim.x + threadIdx.x) >> 5;
    int lane = threadIdx.x & 31;
    if (warp >= N_NODES) return;
    int beg = g_row_ptr[warp];
    int end = g_row_ptr[warp + 1];
    float a0 = 0.f, a1 = 0.f, a2 = 0.f, a3 = 0.f;
    int e = beg;
    for (; e + 4 <= end; e += 4) {
        int u0 = __ldg(&g_csr_src[e]);
        int u1 = __ldg(&g_csr_src[e + 1]);
        int u2 = __ldg(&g_csr_src[e + 2]);
        int u3 = __ldg(&g_csr_src[e + 3]);
        uint2 v0 = __ldg((const uint2*)&hsrc[(long)u0 * D + lane * 4]);
        uint2 v1 = __ldg((const uint2*)&hsrc[(long)u1 * D + lane * 4]);
        uint2 v2 = __ldg((const uint2*)&hsrc[(long)u2 * D + lane * 4]);
        uint2 v3 = __ldg((const uint2*)&hsrc[(long)u3 * D + lane * 4]);
#pragma unroll
        for (int j = 0; j < 4; j++) {
            uint2 v = (j == 0) ? v0 : (j == 1) ? v1 : (j == 2) ? v2 : v3;
            float2 p0 = __half22float2(*(__half2*)&v.x);
            float2 p1 = __half22float2(*(__half2*)&v.y);
            a0 += p0.x; a1 += p0.y; a2 += p1.x; a3 += p1.y;
        }
    }
    for (; e < end; e++) {
        int u = __ldg(&g_csr_src[e]);
        uint2 v = __ldg((const uint2*)&hsrc[(long)u * D + lane * 4]);
        float2 p0 = __half22float2(*(__half2*)&v.x);
        float2 p1 = __half22float2(*(__half2*)&v.y);
        a0 += p0.x; a1 += p0.y; a2 += p1.x; a3 += p1.y;
    }
    float s = g_inv_deg[warp];
    __half2 o01 = __floats2half2_rn(a0 * s, a1 * s);
    __half2 o23 = __floats2half2_rn(a2 * s, a3 * s);
    long off = (long)warp * D + lane * 4;
    *(uint2*)&g_agg[off] = make_uint2(*(uint32_t*)&o01, *(uint32_t*)&o23);
}

// ---------------- fp16 HMMA persistent dual GEMM: D[128,NOUT] = [x|agg] @ B^T + b ----------------
template <int NOUT, bool RELU, bool WF16, bool WF32>
__global__ void __launch_bounds__(256, 2) gemm_mma(
    const __half* __restrict__ x,
    const __half* __restrict__ Bg,
    const float* __restrict__ bias, int nbias,
    float* __restrict__ out, int ostride,
    __half* __restrict__ o_h, int ntiles) {
    constexpr int KS_B = 264;
    constexpr int KS_A = 136;
    constexpr int MT = (NOUT == 128) ? 2 : 1;
    constexpr int NT = (NOUT == 128) ? 8 : 6;
    constexpr int NP = NT / 2;

    extern __shared__ __half sm[];
    __half* sB = sm;                   // NOUT x 264
    __half* sA = sB + NOUT * KS_B;     // 128 x 136
    float* sbias = (float*)(sA + 128 * KS_A);

    int tid = threadIdx.x;
    int wid = tid >> 5;
    int lane = tid & 31;

    int warpM = (NOUT == 128) ? (wid & 3) * 32 : wid * 16;
    int warpN = (NOUT == 128) ? (wid >> 2) * 64 : 0;

    for (int i = tid; i < NOUT * 32; i += 256) {
        int n = i >> 5;
        int k8 = (i & 31) << 3;
        *(uint4*)&sB[n * KS_B + k8] = *(const uint4*)&Bg[n * 256 + k8];
    }
    if (tid < NOUT) sbias[tid] = (tid < nbias) ? bias[tid] : 0.0f;

    uint32_t uA = s2u(sA), uB = s2u(sB);

    int g = lane >> 3;
    int rA = (g & 1) * 8 + (lane & 7);
    int kA = (g >> 1) * 8;
    int rB4 = (g >> 1) * 8 + (lane & 7);
    int kB4 = (g & 1) * 8;

    int qr = lane >> 2;
    int qc = (lane & 3) * 2;

    for (int tile = blockIdx.x; tile < ntiles; tile += gridDim.x) {
        int m0 = tile * 128;

        float acc[MT][NT][4];
#pragma unroll
        for (int mt = 0; mt < MT; mt++)
#pragma unroll
            for (int nt = 0; nt < NT; nt++)
#pragma unroll
                for (int j = 0; j < 4; j++) acc[mt][nt][j] = 0.0f;

#pragma unroll 1
        for (int c = 0; c < 2; c++) {
            const __half* srcA = (c == 0) ? x : g_agg;
            __syncthreads();
            for (int i = tid; i < 128 * 16; i += 256) {
                int r = i >> 4;
                int k8 = (i & 15) << 3;
                int m = m0 + r;
                uint4 v = make_uint4(0, 0, 0, 0);
                if (m < N_NODES) v = *(const uint4*)&srcA[(long)m * 128 + k8];
                *(uint4*)&sA[r * KS_A + k8] = v;
            }
            __syncthreads();

#pragma unroll
            for (int kk = 0; kk < 128; kk += 16) {
                uint32_t a[MT][4];
#pragma unroll
                for (int mt = 0; mt < MT; mt++) {
                    uint32_t off = (uint32_t)((warpM + mt * 16 + rA) * KS_A + kk + kA) * 2;
                    ldsm_x4(a[mt][0], a[mt][1], a[mt][2], a[mt][3], uA + off);
                }
                uint32_t b[NT][2];
#pragma unroll
                for (int p = 0; p < NP; p++) {
                    uint32_t off =
                        (uint32_t)((warpN + p * 16 + rB4) * KS_B + c * 128 + kk + kB4) * 2;
                    ldsm_x4(b[2 * p][0], b[2 * p][1], b[2 * p + 1][0], b[2 * p + 1][1], uB + off);
                }
#pragma unroll
                for (int mt = 0; mt < MT; mt++)
#pragma unroll
                    for (int nt = 0; nt < NT; nt++) mma_f16(acc[mt][nt], a[mt], b[nt]);
            }
        }

#pragma unroll
        for (int mt = 0; mt < MT; mt++) {
#pragma unroll
            for (int nt = 0; nt < NT; nt++) {
                int n = warpN + nt * 8 + qc;
                float bn0 = sbias[n], bn1 = sbias[n + 1];
#pragma unroll
                for (int half = 0; half < 2; half++) {
                    int m = m0 + warpM + mt * 16 + qr + half * 8;
                    if (m >= N_NODES) continue;
                    float v0 = acc[mt][nt][half * 2 + 0] + bn0;
                    float v1 = acc[mt][nt][half * 2 + 1] + bn1;
                    if (RELU) { v0 = fmaxf(v0, 0.0f); v1 = fmaxf(v1, 0.0f); }
                    if (WF16) {
                        __half2 hv = __floats2half2_rn(v0, v1);
                        *(uint32_t*)&o_h[(long)m * 128 + n] = *(uint32_t*)&hv;
                    }
                    if (WF32) {
                        if (NOUT == 128) {
                            *(float2*)&out[(long)m * ostride + n] = make_float2(v0, v1);
                        } else {
                            if (n < N_CLS) out[(long)m * ostride + n] = v0;
                            if (n + 1 < N_CLS) out[(long)m * ostride + n + 1] = v1;
                        }
                    }
                }
            }
        }
    }
}

// ---------------- launch ----------------
extern "C" void kernel_launch(void* const* d_in, const int* in_sizes, int n_in,
                              void* d_out, int out_size) {
    const float* features = (const float*)d_in[0];
    const int*   src      = (const int*)d_in[1];
    const int*   dst      = (const int*)d_in[2];
    const float* Ws0 = (const float*)d_in[3];
    const float* Wn0 = (const float*)d_in[4];
    const float* b0  = (const float*)d_in[5];
    const float* Ws1 = (const float*)d_in[6];
    const float* Wn1 = (const float*)d_in[7];
    const float* b1  = (const float*)d_in[8];
    const float* Ws2 = (const float*)d_in[9];
    const float* Wn2 = (const float*)d_in[10];
    const float* b2  = (const float*)d_in[11];
    float* out = (float*)d_out;

    void* p;
    cudaGetSymbolAddress(&p, g_f);   __half* f = (__half*)p;
    cudaGetSymbolAddress(&p, g_h1);  __half* h1 = (__half*)p;
    cudaGetSymbolAddress(&p, g_h2);  __half* h2 = (__half*)p;
    cudaGetSymbolAddress(&p, g_B0);  __half* B0 = (__half*)p;
    cudaGetSymbolAddress(&p, g_B1);  __half* B1 = (__half*)p;
    cudaGetSymbolAddress(&p, g_B2);  __half* B2 = (__half*)p;

    const int SMEM128 = (128 * 264 + 128 * 136) * 2 + 512;  // 102,912
    const int SMEM48  = (48 * 264 + 128 * 136) * 2 + 512;   //  60,672
    cudaFuncSetAttribute(gemm_mma<128, true, true, false>,
                         cudaFuncAttributeMaxDynamicSharedMemorySize, SMEM128);
    cudaFuncSetAttribute(gemm_mma<48, false, false, true>,
                         cudaFuncAttributeMaxDynamicSharedMemorySize, SMEM48);

    // Fork: CSR chain on main stream, fused weight-prep + feature-convert on s2.
    cudaStream_t s2;
    cudaStreamCreateWithFlags(&s2, cudaStreamNonBlocking);
    cudaEvent_t e_fork, e_join;
    cudaEventCreateWithFlags(&e_fork, cudaEventDisableTiming);
    cudaEventCreateWithFlags(&e_join, cudaEventDisableTiming);

    cudaEventRecord(e_fork, 0);
    cudaStreamWaitEvent(s2, e_fork, 0);

    // s2: fused prep + convert (one kernel)
    prep_convert_kernel<<<CONV_BLOCKS + 128 + 128 + 48, 256, 0, s2>>>(
        features, f, Ws0, Wn0, Ws1, Wn1, Ws2, Wn2);
    cudaEventRecord(e_join, s2);

    // main: CSR build (no memset — g_deg is pre-zeroed; scan tail re-zeroes it)
    const int EDGE2_BLOCKS = ((N_EDGES + 1) / 2 + 255) / 256;
    count_rank_kernel<<<EDGE2_BLOCKS, 256>>>(dst);
    scan_fused_kernel<<<SCAN_BLOCKS, SCAN_CHUNK>>>();
    fill_csr_kernel<<<EDGE2_BLOCKS, 256>>>(src, dst);

    cudaStreamWaitEvent(0, e_join, 0);

    const int AGG_BLOCKS = (N_NODES * 32 + 255) / 256;
    const int NTILES = (N_NODES + 127) / 128;  // 391
    const int GEMM_GRID = 296;                 // 2 CTAs/SM persistent

    // Layer 0
    agg_kernel<<<AGG_BLOCKS, 256>>>(f);
    gemm_mma<128, true, true, false><<<GEMM_GRID, 256, SMEM128>>>(
        f, B0, b0, 128, nullptr, 128, h1, NTILES);

    // Layer 1
    agg_kernel<<<AGG_BLOCKS, 256>>>(h1);
    gemm_mma<128, true, true, false><<<GEMM_GRID, 256, SMEM128>>>(
        h1, B1, b1, 128, nullptr, 128, h2, NTILES);

    // Layer 2 (47 classes, no relu, fp32 out)
    agg_kernel<<<AGG_BLOCKS, 256>>>(h2);
    gemm_mma<48, false, false, true><<<GEMM_GRID, 256, SMEM48>>>(
        h2, B2, b2, 47, out, 47, nullptr, NTILES);
}

// round 16
// speedup vs baseline: 1.0845x; 1.0219x over previous
#include <cuda_runtime.h>
#include <cuda_fp16.h>
#include <cstdint>

#define N_NODES 50000
#define N_EDGES 800000
#define D 128
#define N_CLS 47

#define SCAN_CHUNK 512
#define SCAN_BLOCKS ((N_NODES + SCAN_CHUNK - 1) / SCAN_CHUNK)  // 98

#define PDL_TRIGGER() asm volatile("griddepcontrol.launch_dependents;" ::: "memory")
#define PDL_WAIT()    asm volatile("griddepcontrol.wait;" ::: "memory")

// ---------------- scratch (no allocations allowed; zero-initialized at load) ----------------
__device__ int   g_deg[N_NODES];
__device__ int   g_row_ptr[N_NODES + 1];
__device__ int   g_rank[N_EDGES];
__device__ int   g_csr_src[N_EDGES];
__device__ float g_inv_deg[N_NODES];
__device__ int   g_blk_sum[SCAN_BLOCKS];
__device__ int   g_blk_off[SCAN_BLOCKS];
__device__ int   g_arrive;
__device__ volatile int g_flag;

__device__ __half g_f[N_NODES * D];
__device__ __half g_h1[N_NODES * D];
__device__ __half g_h2[N_NODES * D];
__device__ __half g_agg[N_NODES * D];

// Weights pre-transposed + K-concatenated: B[n][k], k in [0,256), fp16
__device__ __half g_B0[128 * 256];
__device__ __half g_B1[128 * 256];
__device__ __half g_B2[48 * 256];

// ---------------- PTX helpers (baseline PTX only) ----------------
__device__ __forceinline__ uint32_t s2u(const void* p) {
    uint32_t a;
    asm("{ .reg .u64 t; cvta.to.shared.u64 t, %1; cvt.u32.u64 %0, t; }" : "=r"(a) : "l"(p));
    return a;
}

__device__ __forceinline__ void ldsm_x4(uint32_t& r0, uint32_t& r1, uint32_t& r2, uint32_t& r3,
                                        uint32_t addr) {
    asm volatile("ldmatrix.sync.aligned.m8n8.x4.shared.b16 {%0,%1,%2,%3}, [%4];"
                 : "=r"(r0), "=r"(r1), "=r"(r2), "=r"(r3) : "r"(addr));
}

__device__ __forceinline__ void mma_f16(float* c, const uint32_t* a, const uint32_t* b) {
    asm volatile(
        "mma.sync.aligned.m16n8k16.row.col.f32.f16.f16.f32 "
        "{%0,%1,%2,%3}, {%4,%5,%6,%7}, {%8,%9}, {%0,%1,%2,%3};"
        : "+f"(c[0]), "+f"(c[1]), "+f"(c[2]), "+f"(c[3])
        : "r"(a[0]), "r"(a[1]), "r"(a[2]), "r"(a[3]), "r"(b[0]), "r"(b[1]));
}

// ---------------- CSR build ----------------
// g_deg enters zeroed (load-time zero-init on call 1, scan-tail zeroing on replays).
__global__ void count_rank_kernel(const int* __restrict__ dst) {
    if (blockIdx.x == 0 && threadIdx.x == 0) { g_arrive = 0; g_flag = 0; }
    int t = blockIdx.x * blockDim.x + threadIdx.x;
    int e = t * 2;
    if (e + 1 < N_EDGES) {
        int2 dd = *(const int2*)&dst[e];
        int r0 = atomicAdd(&g_deg[dd.x], 1);
        int r1 = atomicAdd(&g_deg[dd.y], 1);
        *(int2*)&g_rank[e] = make_int2(r0, r1);
    } else if (e < N_EDGES) {
        g_rank[e] = atomicAdd(&g_deg[dst[e]], 1);
    }
}

// Shuffle-based fused scan with nanosleep-backoff spin.
// Tail also zeroes this block's g_deg chunk for the next graph replay.
__global__ void scan_fused_kernel() {
    __shared__ int wsum[16];
    __shared__ int sh_is_last;
    int tid = threadIdx.x;
    int lane = tid & 31;
    int w = tid >> 5;
    int b = blockIdx.x;
    int i = b * SCAN_CHUNK + tid;
    int d = (i < N_NODES) ? g_deg[i] : 0;

    int v = d;
#pragma unroll
    for (int off = 1; off < 32; off <<= 1) {
        int t = __shfl_up_sync(0xffffffffu, v, off);
        if (lane >= off) v += t;
    }
    if (lane == 31) wsum[w] = v;
    __syncthreads();
    if (w == 0) {
        int x = (lane < 16) ? wsum[lane] : 0;
#pragma unroll
        for (int off = 1; off < 16; off <<= 1) {
            int t = __shfl_up_sync(0xffffffffu, x, off);
            if (lane >= off) x += t;
        }
        if (lane < 16) wsum[lane] = x;
    }
    __syncthreads();
    int incl = v + ((w > 0) ? wsum[w - 1] : 0);
    int blocksum = wsum[15];

    if (tid == 0) {
        g_blk_sum[b] = blocksum;
        __threadfence();
        int t = atomicAdd(&g_arrive, 1);
        sh_is_last = (t == SCAN_BLOCKS - 1) ? 1 : 0;
    }
    __syncthreads();

    if (sh_is_last && w == 0) {
        int base = lane * 4;
        int s[4];
        int tot = 0;
#pragma unroll
        for (int j = 0; j < 4; j++) {
            s[j] = (base + j < SCAN_BLOCKS) ? g_blk_sum[base + j] : 0;
            tot += s[j];
        }
        int ex = tot;
#pragma unroll
        for (int off = 1; off < 32; off <<= 1) {
            int t = __shfl_up_sync(0xffffffffu, ex, off);
            if (lane >= off) ex += t;
        }
        ex -= tot;
        int run = ex;
#pragma unroll
        for (int j = 0; j < 4; j++) {
            if (base + j < SCAN_BLOCKS) g_blk_off[base + j] = run;
            run += s[j];
        }
        if (lane == 0) g_row_ptr[N_NODES] = N_EDGES;
        __threadfence();
        __syncwarp();
        if (lane == 0) g_flag = 1;
    }

    if (tid == 0) {
        while (g_flag == 0) { __nanosleep(256); }
    }
    __syncthreads();

    if (i < N_NODES) {
        int excl = g_blk_off[b] + incl - d;
        g_row_ptr[i] = excl;
        g_inv_deg[i] = 1.0f / (float)(d > 1 ? d : 1);
        g_deg[i] = 0;   // ready for next replay (only this block reads this chunk)
    }
}

// Atomic-free fill, 2 edges per thread.
__global__ void fill_csr_kernel(const int* __restrict__ src, const int* __restrict__ dst) {
    int t = blockIdx.x * blockDim.x + threadIdx.x;
    int e = t * 2;
    if (e + 1 < N_EDGES) {
        int2 dd = *(const int2*)&dst[e];
        int2 rr = *(const int2*)&g_rank[e];
        int2 ss = *(const int2*)&src[e];
        g_csr_src[__ldg(&g_row_ptr[dd.x]) + rr.x] = ss.x;
        g_csr_src[__ldg(&g_row_ptr[dd.y]) + rr.y] = ss.y;
    } else if (e < N_EDGES) {
        g_csr_src[__ldg(&g_row_ptr[dst[e]]) + g_rank[e]] = src[e];
    }
}

// ---------------- fused weight prep (3 layers) + feature fp32->fp16 convert ----------------
#define CONV_BLOCKS ((N_NODES * D + 255) / 256)   // 25000
__global__ void prep_convert_kernel(const float* __restrict__ x, __half* __restrict__ o,
                                    const float* __restrict__ Ws0, const float* __restrict__ Wn0,
                                    const float* __restrict__ Ws1, const float* __restrict__ Wn1,
                                    const float* __restrict__ Ws2, const float* __restrict__ Wn2) {
    int bid = blockIdx.x;
    if (bid < CONV_BLOCKS) {
        int i = bid * blockDim.x + threadIdx.x;
        if (i < N_NODES * D) o[i] = __float2half_rn(x[i]);
        return;
    }
    int pb = bid - CONV_BLOCKS;
    const float* Ws;
    const float* Wn;
    __half* B;
    int nreal, npad;
    if (pb < 128) { Ws = Ws0; Wn = Wn0; B = g_B0; nreal = 128; npad = 128; }
    else if (pb < 256) { pb -= 128; Ws = Ws1; Wn = Wn1; B = g_B1; nreal = 128; npad = 128; }
    else { pb -= 256; Ws = Ws2; Wn = Wn2; B = g_B2; nreal = 47; npad = 48; }
    int i = pb * blockDim.x + threadIdx.x;
    if (i >= npad * 256) return;
    int n = i / 256, k = i % 256;
    float w = 0.0f;
    if (n < nreal) w = (k < 128) ? Ws[k * nreal + n] : Wn[(k - 128) * nreal + n];
    B[i] = __float2half_rn(w);
}

// ---------------- mean aggregation over fp16 rows: one warp per node ----------------
// PDL: trigger immediately (lets next gemm pre-load B), then wait for producer of hsrc.
__global__ void agg_kernel(const __half* __restrict__ hsrc) {
    PDL_TRIGGER();
    PDL_WAIT();
    int warp = (blockIdx.x * blockDim.x + threadIdx.x) >> 5;
    int lane = threadIdx.x & 31;
    if (warp >= N_NODES) return;
    int beg = g_row_ptr[warp];
    int end = g_row_ptr[warp + 1];
    float a0 = 0.f, a1 = 0.f, a2 = 0.f, a3 = 0.f;
    int e = beg;
    for (; e + 4 <= end; e += 4) {
        int u0 = __ldg(&g_csr_src[e]);
        int u1 = __ldg(&g_csr_src[e + 1]);
        int u2 = __ldg(&g_csr_src[e + 2]);
        int u3 = __ldg(&g_csr_src[e + 3]);
        uint2 v0 = __ldg((const uint2*)&hsrc[(long)u0 * D + lane * 4]);
        uint2 v1 = __ldg((const uint2*)&hsrc[(long)u1 * D + lane * 4]);
        uint2 v2 = __ldg((const uint2*)&hsrc[(long)u2 * D + lane * 4]);
        uint2 v3 = __ldg((const uint2*)&hsrc[(long)u3 * D + lane * 4]);
#pragma unroll
        for (int j = 0; j < 4; j++) {
            uint2 v = (j == 0) ? v0 : (j == 1) ? v1 : (j == 2) ? v2 : v3;
            float2 p0 = __half22float2(*(__half2*)&v.x);
            float2 p1 = __half22float2(*(__half2*)&v.y);
            a0 += p0.x; a1 += p0.y; a2 += p1.x; a3 += p1.y;
        }
    }
    for (; e < end; e++) {
        int u = __ldg(&g_csr_src[e]);
        uint2 v = __ldg((const uint2*)&hsrc[(long)u * D + lane * 4]);
        float2 p0 = __half22float2(*(__half2*)&v.x);
        float2 p1 = __half22float2(*(__half2*)&v.y);
        a0 += p0.x; a1 += p0.y; a2 += p1.x; a3 += p1.y;
    }
    float s = g_inv_deg[warp];
    __half2 o01 = __floats2half2_rn(a0 * s, a1 * s);
    __half2 o23 = __floats2half2_rn(a2 * s, a3 * s);
    long off = (long)warp * D + lane * 4;
    *(uint2*)&g_agg[off] = make_uint2(*(uint32_t*)&o01, *(uint32_t*)&o23);
}

// ---------------- fp16 HMMA persistent dual GEMM: D[128,NOUT] = [x|agg] @ B^T + b ----------------
// PDL: trigger at entry; load B/bias (written in preamble, safe) BEFORE waiting on agg.
template <int NOUT, bool RELU, bool WF16, bool WF32>
__global__ void __launch_bounds__(256, 2) gemm_mma(
    const __half* __restrict__ x,
    const __half* __restrict__ Bg,
    const float* __restrict__ bias, int nbias,
    float* __restrict__ out, int ostride,
    __half* __restrict__ o_h, int ntiles) {
    constexpr int KS_B = 264;
    constexpr int KS_A = 136;
    constexpr int MT = (NOUT == 128) ? 2 : 1;
    constexpr int NT = (NOUT == 128) ? 8 : 6;
    constexpr int NP = NT / 2;

    extern __shared__ __half sm[];
    __half* sB = sm;                   // NOUT x 264
    __half* sA = sB + NOUT * KS_B;     // 128 x 136
    float* sbias = (float*)(sA + 128 * KS_A);

    PDL_TRIGGER();

    int tid = threadIdx.x;
    int wid = tid >> 5;
    int lane = tid & 31;

    int warpM = (NOUT == 128) ? (wid & 3) * 32 : wid * 16;
    int warpN = (NOUT == 128) ? (wid >> 2) * 64 : 0;

    // B + bias load overlaps the still-running agg (pre-wait; data is preamble-written)
    for (int i = tid; i < NOUT * 32; i += 256) {
        int n = i >> 5;
        int k8 = (i & 31) << 3;
        *(uint4*)&sB[n * KS_B + k8] = *(const uint4*)&Bg[n * 256 + k8];
    }
    if (tid < NOUT) sbias[tid] = (tid < nbias) ? bias[tid] : 0.0f;

    PDL_WAIT();

    uint32_t uA = s2u(sA), uB = s2u(sB);

    int g = lane >> 3;
    int rA = (g & 1) * 8 + (lane & 7);
    int kA = (g >> 1) * 8;
    int rB4 = (g >> 1) * 8 + (lane & 7);
    int kB4 = (g & 1) * 8;

    int qr = lane >> 2;
    int qc = (lane & 3) * 2;

    for (int tile = blockIdx.x; tile < ntiles; tile += gridDim.x) {
        int m0 = tile * 128;

        float acc[MT][NT][4];
#pragma unroll
        for (int mt = 0; mt < MT; mt++)
#pragma unroll
            for (int nt = 0; nt < NT; nt++)
#pragma unroll
                for (int j = 0; j < 4; j++) acc[mt][nt][j] = 0.0f;

#pragma unroll 1
        for (int c = 0; c < 2; c++) {
            const __half* srcA = (c == 0) ? x : g_agg;
            __syncthreads();
            for (int i = tid; i < 128 * 16; i += 256) {
                int r = i >> 4;
                int k8 = (i & 15) << 3;
                int m = m0 + r;
                uint4 v = make_uint4(0, 0, 0, 0);
                if (m < N_NODES) v = *(const uint4*)&srcA[(long)m * 128 + k8];
                *(uint4*)&sA[r * KS_A + k8] = v;
            }
            __syncthreads();

#pragma unroll
            for (int kk = 0; kk < 128; kk += 16) {
                uint32_t a[MT][4];
#pragma unroll
                for (int mt = 0; mt < MT; mt++) {
                    uint32_t off = (uint32_t)((warpM + mt * 16 + rA) * KS_A + kk + kA) * 2;
                    ldsm_x4(a[mt][0], a[mt][1], a[mt][2], a[mt][3], uA + off);
                }
                uint32_t b[NT][2];
#pragma unroll
                for (int p = 0; p < NP; p++) {
                    uint32_t off =
                        (uint32_t)((warpN + p * 16 + rB4) * KS_B + c * 128 + kk + kB4) * 2;
                    ldsm_x4(b[2 * p][0], b[2 * p][1], b[2 * p + 1][0], b[2 * p + 1][1], uB + off);
                }
#pragma unroll
                for (int mt = 0; mt < MT; mt++)
#pragma unroll
                    for (int nt = 0; nt < NT; nt++) mma_f16(acc[mt][nt], a[mt], b[nt]);
            }
        }

#pragma unroll
        for (int mt = 0; mt < MT; mt++) {
#pragma unroll
            for (int nt = 0; nt < NT; nt++) {
                int n = warpN + nt * 8 + qc;
                float bn0 = sbias[n], bn1 = sbias[n + 1];
#pragma unroll
                for (int half = 0; half < 2; half++) {
                    int m = m0 + warpM + mt * 16 + qr + half * 8;
                    if (m >= N_NODES) continue;
                    float v0 = acc[mt][nt][half * 2 + 0] + bn0;
                    float v1 = acc[mt][nt][half * 2 + 1] + bn1;
                    if (RELU) { v0 = fmaxf(v0, 0.0f); v1 = fmaxf(v1, 0.0f); }
                    if (WF16) {
                        __half2 hv = __floats2half2_rn(v0, v1);
                        *(uint32_t*)&o_h[(long)m * 128 + n] = *(uint32_t*)&hv;
                    }
                    if (WF32) {
                        if (NOUT == 128) {
                            *(float2*)&out[(long)m * ostride + n] = make_float2(v0, v1);
                        } else {
                            if (n < N_CLS) out[(long)m * ostride + n] = v0;
                            if (n + 1 < N_CLS) out[(long)m * ostride + n + 1] = v1;
                        }
                    }
                }
            }
        }
    }
}

// ---------------- PDL launch helper ----------------
template <typename K, typename... Args>
static void launch_pdl(K kernel, dim3 grid, dim3 block, size_t smem, cudaStream_t stream,
                       Args... args) {
    cudaLaunchConfig_t cfg = {};
    cfg.gridDim = grid;
    cfg.blockDim = block;
    cfg.dynamicSmemBytes = smem;
    cfg.stream = stream;
    cudaLaunchAttribute at[1];
    at[0].id = cudaLaunchAttributeProgrammaticStreamSerialization;
    at[0].val.programmaticStreamSerializationAllowed = 1;
    cfg.attrs = at;
    cfg.numAttrs = 1;
    cudaLaunchKernelEx(&cfg, kernel, args...);
}

// ---------------- launch ----------------
extern "C" void kernel_launch(void* const* d_in, const int* in_sizes, int n_in,
                              void* d_out, int out_size) {
    const float* features = (const float*)d_in[0];
    const int*   src      = (const int*)d_in[1];
    const int*   dst      = (const int*)d_in[2];
    const float* Ws0 = (const float*)d_in[3];
    const float* Wn0 = (const float*)d_in[4];
    const float* b0  = (const float*)d_in[5];
    const float* Ws1 = (const float*)d_in[6];
    const float* Wn1 = (const float*)d_in[7];
    const float* b1  = (const float*)d_in[8];
    const float* Ws2 = (const float*)d_in[9];
    const float* Wn2 = (const float*)d_in[10];
    const float* b2  = (const float*)d_in[11];
    float* out = (float*)d_out;

    void* p;
    cudaGetSymbolAddress(&p, g_f);   __half* f = (__half*)p;
    cudaGetSymbolAddress(&p, g_h1);  __half* h1 = (__half*)p;
    cudaGetSymbolAddress(&p, g_h2);  __half* h2 = (__half*)p;
    cudaGetSymbolAddress(&p, g_B0);  __half* B0 = (__half*)p;
    cudaGetSymbolAddress(&p, g_B1);  __half* B1 = (__half*)p;
    cudaGetSymbolAddress(&p, g_B2);  __half* B2 = (__half*)p;

    const int SMEM128 = (128 * 264 + 128 * 136) * 2 + 512;  // 102,912
    const int SMEM48  = (48 * 264 + 128 * 136) * 2 + 512;   //  60,672
    cudaFuncSetAttribute(gemm_mma<128, true, true, false>,
                         cudaFuncAttributeMaxDynamicSharedMemorySize, SMEM128);
    cudaFuncSetAttribute(gemm_mma<48, false, false, true>,
                         cudaFuncAttributeMaxDynamicSharedMemorySize, SMEM48);

    // Fork: CSR chain on main stream, fused weight-prep + feature-convert on s2.
    cudaStream_t s2;
    cudaStreamCreateWithFlags(&s2, cudaStreamNonBlocking);
    cudaEvent_t e_fork, e_join;
    cudaEventCreateWithFlags(&e_fork, cudaEventDisableTiming);
    cudaEventCreateWithFlags(&e_join, cudaEventDisableTiming);

    cudaEventRecord(e_fork, 0);
    cudaStreamWaitEvent(s2, e_fork, 0);

    // s2: fused prep + convert (one kernel)
    prep_convert_kernel<<<CONV_BLOCKS + 128 + 128 + 48, 256, 0, s2>>>(
        features, f, Ws0, Wn0, Ws1, Wn1, Ws2, Wn2);
    cudaEventRecord(e_join, s2);

    // main: CSR build (normal launches; no memset — g_deg pre-zeroed, scan tail re-zeroes)
    const int EDGE2_BLOCKS = ((N_EDGES + 1) / 2 + 255) / 256;
    count_rank_kernel<<<EDGE2_BLOCKS, 256>>>(dst);
    scan_fused_kernel<<<SCAN_BLOCKS, SCAN_CHUNK>>>();
    fill_csr_kernel<<<EDGE2_BLOCKS, 256>>>(src, dst);

    cudaStreamWaitEvent(0, e_join, 0);

    const int AGG_BLOCKS = (N_NODES * 32 + 255) / 256;
    const int NTILES = (N_NODES + 127) / 128;  // 391
    const int GEMM_GRID = 296;                 // 2 CTAs/SM persistent

    // Layer chain with PDL overlap at each boundary
    launch_pdl(agg_kernel, AGG_BLOCKS, 256, 0, (cudaStream_t)0, f);
    launch_pdl(gemm_mma<128, true, true, false>, GEMM_GRID, 256, SMEM128, (cudaStream_t)0,
               (const __half*)f, (const __half*)B0, b0, 128, (float*)nullptr, 128,
               (__half*)h1, NTILES);

    launch_pdl(agg_kernel, AGG_BLOCKS, 256, 0, (cudaStream_t)0, (const __half*)h1);
    launch_pdl(gemm_mma<128, true, true, false>, GEMM_GRID, 256, SMEM128, (cudaStream_t)0,
               (const __half*)h1, (const __half*)B1, b1, 128, (float*)nullptr, 128,
               (__half*)h2, NTILES);

    launch_pdl(agg_kernel, AGG_BLOCKS, 256, 0, (cudaStream_t)0, (const __half*)h2);
    launch_pdl(gemm_mma<48, false, false, true>, GEMM_GRID, 256, SMEM48, (cudaStream_t)0,
               (const __half*)h2, (const __half*)B2, b2, 47, out, 47,
               (__half*)nullptr, NTILES);
}

// round 17
// speedup vs baseline: 1.0935x; 1.0083x over previous
#include <cuda_runtime.h>
#include <cuda_fp16.h>
#include <cstdint>

#define N_NODES 50000
#define N_EDGES 800000
#define D 128
#define N_CLS 47

#define SCAN_CHUNK 512
#define SCAN_BLOCKS ((N_NODES + SCAN_CHUNK - 1) / SCAN_CHUNK)  // 98

#define PDL_TRIGGER() asm volatile("griddepcontrol.launch_dependents;" ::: "memory")
#define PDL_WAIT()    asm volatile("griddepcontrol.wait;" ::: "memory")

// ---------------- scratch (no allocations allowed; zero-initialized at load) ----------------
__device__ int   g_deg[N_NODES];
__device__ int   g_row_ptr[N_NODES + 1];
__device__ int   g_rank[N_EDGES];
__device__ int   g_csr_src[N_EDGES];
__device__ float g_inv_deg[N_NODES];
__device__ int   g_blk_sum[SCAN_BLOCKS];
__device__ int   g_blk_off[SCAN_BLOCKS];
__device__ int   g_arrive;
__device__ volatile int g_flag;

__device__ __half g_f[N_NODES * D];
__device__ __half g_h1[N_NODES * D];
__device__ __half g_h2[N_NODES * D];
__device__ __half g_agg[N_NODES * D];

// Weights pre-transposed + K-concatenated: B[n][k], k in [0,256), fp16
__device__ __half g_B0[128 * 256];
__device__ __half g_B1[128 * 256];
__device__ __half g_B2[48 * 256];

// ---------------- PTX helpers (baseline PTX only) ----------------
__device__ __forceinline__ uint32_t s2u(const void* p) {
    uint32_t a;
    asm("{ .reg .u64 t; cvta.to.shared.u64 t, %1; cvt.u32.u64 %0, t; }" : "=r"(a) : "l"(p));
    return a;
}

__device__ __forceinline__ void ldsm_x4(uint32_t& r0, uint32_t& r1, uint32_t& r2, uint32_t& r3,
                                        uint32_t addr) {
    asm volatile("ldmatrix.sync.aligned.m8n8.x4.shared.b16 {%0,%1,%2,%3}, [%4];"
                 : "=r"(r0), "=r"(r1), "=r"(r2), "=r"(r3) : "r"(addr));
}

__device__ __forceinline__ void mma_f16(float* c, const uint32_t* a, const uint32_t* b) {
    asm volatile(
        "mma.sync.aligned.m16n8k16.row.col.f32.f16.f16.f32 "
        "{%0,%1,%2,%3}, {%4,%5,%6,%7}, {%8,%9}, {%0,%1,%2,%3};"
        : "+f"(c[0]), "+f"(c[1]), "+f"(c[2]), "+f"(c[3])
        : "r"(a[0]), "r"(a[1]), "r"(a[2]), "r"(a[3]), "r"(b[0]), "r"(b[1]));
}

// ---------------- CSR build ----------------
// g_deg enters zeroed (load-time zero-init on call 1, scan-tail zeroing on replays).
__global__ void count_rank_kernel(const int* __restrict__ dst) {
    PDL_TRIGGER();   // let scan launch early (it waits before touching g_deg)
    if (blockIdx.x == 0 && threadIdx.x == 0) { g_arrive = 0; g_flag = 0; }
    int t = blockIdx.x * blockDim.x + threadIdx.x;
    int e = t * 2;
    if (e + 1 < N_EDGES) {
        int2 dd = *(const int2*)&dst[e];
        int r0 = atomicAdd(&g_deg[dd.x], 1);
        int r1 = atomicAdd(&g_deg[dd.y], 1);
        *(int2*)&g_rank[e] = make_int2(r0, r1);
    } else if (e < N_EDGES) {
        g_rank[e] = atomicAdd(&g_deg[dst[e]], 1);
    }
}

// Shuffle-based fused scan. PDL: wait for count, then trigger so fill can launch
// (g_rank final at fill's launch) and prefetch while scan computes.
__global__ void scan_fused_kernel() {
    __shared__ int wsum[16];
    __shared__ int sh_is_last;
    PDL_WAIT();      // count complete -> g_deg/g_rank final
    PDL_TRIGGER();   // fill may launch and prefetch src/dst/rank
    int tid = threadIdx.x;
    int lane = tid & 31;
    int w = tid >> 5;
    int b = blockIdx.x;
    int i = b * SCAN_CHUNK + tid;
    int d = (i < N_NODES) ? g_deg[i] : 0;

    int v = d;
#pragma unroll
    for (int off = 1; off < 32; off <<= 1) {
        int t = __shfl_up_sync(0xffffffffu, v, off);
        if (lane >= off) v += t;
    }
    if (lane == 31) wsum[w] = v;
    __syncthreads();
    if (w == 0) {
        int x = (lane < 16) ? wsum[lane] : 0;
#pragma unroll
        for (int off = 1; off < 16; off <<= 1) {
            int t = __shfl_up_sync(0xffffffffu, x, off);
            if (lane >= off) x += t;
        }
        if (lane < 16) wsum[lane] = x;
    }
    __syncthreads();
    int incl = v + ((w > 0) ? wsum[w - 1] : 0);
    int blocksum = wsum[15];

    if (tid == 0) {
        g_blk_sum[b] = blocksum;
        __threadfence();
        int t = atomicAdd(&g_arrive, 1);
        sh_is_last = (t == SCAN_BLOCKS - 1) ? 1 : 0;
    }
    __syncthreads();

    if (sh_is_last && w == 0) {
        int base = lane * 4;
        int s[4];
        int tot = 0;
#pragma unroll
        for (int j = 0; j < 4; j++) {
            s[j] = (base + j < SCAN_BLOCKS) ? g_blk_sum[base + j] : 0;
            tot += s[j];
        }
        int ex = tot;
#pragma unroll
        for (int off = 1; off < 32; off <<= 1) {
            int t = __shfl_up_sync(0xffffffffu, ex, off);
            if (lane >= off) ex += t;
        }
        ex -= tot;
        int run = ex;
#pragma unroll
        for (int j = 0; j < 4; j++) {
            if (base + j < SCAN_BLOCKS) g_blk_off[base + j] = run;
            run += s[j];
        }
        if (lane == 0) g_row_ptr[N_NODES] = N_EDGES;
        __threadfence();
        __syncwarp();
        if (lane == 0) g_flag = 1;
    }

    if (tid == 0) {
        while (g_flag == 0) { __nanosleep(256); }
    }
    __syncthreads();

    if (i < N_NODES) {
        int excl = g_blk_off[b] + incl - d;
        g_row_ptr[i] = excl;
        g_inv_deg[i] = 1.0f / (float)(d > 1 ? d : 1);
        g_deg[i] = 0;   // ready for next replay (only this block reads this chunk)
    }
}

// Atomic-free fill, 2 edges per thread.
// PDL: prefetch src/dst/rank BEFORE waiting (final at launch: scan triggered post-wait),
// then wait for scan's row_ptr, then store. Trigger lets agg0 launch with row_ptr final.
__global__ void fill_csr_kernel(const int* __restrict__ src, const int* __restrict__ dst) {
    int t = blockIdx.x * blockDim.x + threadIdx.x;
    int e = t * 2;
    int2 dd = make_int2(0, 0), rr = make_int2(0, 0), ss = make_int2(0, 0);
    bool full = (e + 1 < N_EDGES), one = (!full && e < N_EDGES);
    if (full) {
        dd = *(const int2*)&dst[e];
        rr = *(const int2*)&g_rank[e];
        ss = *(const int2*)&src[e];
    } else if (one) {
        dd.x = dst[e];
        rr.x = g_rank[e];
        ss.x = src[e];
    }
    PDL_WAIT();      // scan complete -> row_ptr final
    PDL_TRIGGER();   // agg0 may launch and prefetch row_ptr/inv_deg
    if (full) {
        g_csr_src[__ldg(&g_row_ptr[dd.x]) + rr.x] = ss.x;
        g_csr_src[__ldg(&g_row_ptr[dd.y]) + rr.y] = ss.y;
    } else if (one) {
        g_csr_src[__ldg(&g_row_ptr[dd.x]) + rr.x] = ss.x;
    }
}

// ---------------- fused weight prep (3 layers) + feature fp32->fp16 convert ----------------
#define CONV_BLOCKS ((N_NODES * D + 255) / 256)   // 25000
__global__ void prep_convert_kernel(const float* __restrict__ x, __half* __restrict__ o,
                                    const float* __restrict__ Ws0, const float* __restrict__ Wn0,
                                    const float* __restrict__ Ws1, const float* __restrict__ Wn1,
                                    const float* __restrict__ Ws2, const float* __restrict__ Wn2) {
    int bid = blockIdx.x;
    if (bid < CONV_BLOCKS) {
        int i = bid * blockDim.x + threadIdx.x;
        if (i < N_NODES * D) o[i] = __float2half_rn(x[i]);
        return;
    }
    int pb = bid - CONV_BLOCKS;
    const float* Ws;
    const float* Wn;
    __half* B;
    int nreal, npad;
    if (pb < 128) { Ws = Ws0; Wn = Wn0; B = g_B0; nreal = 128; npad = 128; }
    else if (pb < 256) { pb -= 128; Ws = Ws1; Wn = Wn1; B = g_B1; nreal = 128; npad = 128; }
    else { pb -= 256; Ws = Ws2; Wn = Wn2; B = g_B2; nreal = 47; npad = 48; }
    int i = pb * blockDim.x + threadIdx.x;
    if (i >= npad * 256) return;
    int n = i / 256, k = i % 256;
    float w = 0.0f;
    if (n < nreal) w = (k < 128) ? Ws[k * nreal + n] : Wn[(k - 128) * nreal + n];
    B[i] = __float2half_rn(w);
}

// ---------------- mean aggregation over fp16 rows: one warp per node ----------------
// PDL: trigger at entry (next gemm pre-loads B); prefetch CSR metadata (final at launch)
// before waiting on the producer of hsrc.
__global__ void agg_kernel(const __half* __restrict__ hsrc) {
    PDL_TRIGGER();
    int warp = (blockIdx.x * blockDim.x + threadIdx.x) >> 5;
    int lane = threadIdx.x & 31;
    bool valid = warp < N_NODES;
    int beg = 0, end = 0;
    float s = 0.0f;
    if (valid) {
        beg = __ldg(&g_row_ptr[warp]);
        end = __ldg(&g_row_ptr[warp + 1]);
        s = __ldg(&g_inv_deg[warp]);
    }
    PDL_WAIT();
    if (!valid) return;
    float a0 = 0.f, a1 = 0.f, a2 = 0.f, a3 = 0.f;
    int e = beg;
    for (; e + 4 <= end; e += 4) {
        int u0 = __ldg(&g_csr_src[e]);
        int u1 = __ldg(&g_csr_src[e + 1]);
        int u2 = __ldg(&g_csr_src[e + 2]);
        int u3 = __ldg(&g_csr_src[e + 3]);
        uint2 v0 = __ldg((const uint2*)&hsrc[(long)u0 * D + lane * 4]);
        uint2 v1 = __ldg((const uint2*)&hsrc[(long)u1 * D + lane * 4]);
        uint2 v2 = __ldg((const uint2*)&hsrc[(long)u2 * D + lane * 4]);
        uint2 v3 = __ldg((const uint2*)&hsrc[(long)u3 * D + lane * 4]);
#pragma unroll
        for (int j = 0; j < 4; j++) {
            uint2 v = (j == 0) ? v0 : (j == 1) ? v1 : (j == 2) ? v2 : v3;
            float2 p0 = __half22float2(*(__half2*)&v.x);
            float2 p1 = __half22float2(*(__half2*)&v.y);
            a0 += p0.x; a1 += p0.y; a2 += p1.x; a3 += p1.y;
        }
    }
    for (; e < end; e++) {
        int u = __ldg(&g_csr_src[e]);
        uint2 v = __ldg((const uint2*)&hsrc[(long)u * D + lane * 4]);
        float2 p0 = __half22float2(*(__half2*)&v.x);
        float2 p1 = __half22float2(*(__half2*)&v.y);
        a0 += p0.x; a1 += p0.y; a2 += p1.x; a3 += p1.y;
    }
    __half2 o01 = __floats2half2_rn(a0 * s, a1 * s);
    __half2 o23 = __floats2half2_rn(a2 * s, a3 * s);
    long off = (long)warp * D + lane * 4;
    *(uint2*)&g_agg[off] = make_uint2(*(uint32_t*)&o01, *(uint32_t*)&o23);
}

// ---------------- fp16 HMMA persistent dual GEMM: D[128,NOUT] = [x|agg] @ B^T + b ----------------
// PDL: trigger at entry; load B/bias (preamble-written, safe) BEFORE waiting on agg.
template <int NOUT, bool RELU, bool WF16, bool WF32>
__global__ void __launch_bounds__(256, 2) gemm_mma(
    const __half* __restrict__ x,
    const __half* __restrict__ Bg,
    const float* __restrict__ bias, int nbias,
    float* __restrict__ out, int ostride,
    __half* __restrict__ o_h, int ntiles) {
    constexpr int KS_B = 264;
    constexpr int KS_A = 136;
    constexpr int MT = (NOUT == 128) ? 2 : 1;
    constexpr int NT = (NOUT == 128) ? 8 : 6;
    constexpr int NP = NT / 2;

    extern __shared__ __half sm[];
    __half* sB = sm;                   // NOUT x 264
    __half* sA = sB + NOUT * KS_B;     // 128 x 136
    float* sbias = (float*)(sA + 128 * KS_A);

    PDL_TRIGGER();

    int tid = threadIdx.x;
    int wid = tid >> 5;
    int lane = tid & 31;

    int warpM = (NOUT == 128) ? (wid & 3) * 32 : wid * 16;
    int warpN = (NOUT == 128) ? (wid >> 2) * 64 : 0;

    for (int i = tid; i < NOUT * 32; i += 256) {
        int n = i >> 5;
        int k8 = (i & 31) << 3;
        *(uint4*)&sB[n * KS_B + k8] = *(const uint4*)&Bg[n * 256 + k8];
    }
    if (tid < NOUT) sbias[tid] = (tid < nbias) ? bias[tid] : 0.0f;

    PDL_WAIT();

    uint32_t uA = s2u(sA), uB = s2u(sB);

    int g = lane >> 3;
    int rA = (g & 1) * 8 + (lane & 7);
    int kA = (g >> 1) * 8;
    int rB4 = (g >> 1) * 8 + (lane & 7);
    int kB4 = (g & 1) * 8;

    int qr = lane >> 2;
    int qc = (lane & 3) * 2;

    for (int tile = blockIdx.x; tile < ntiles; tile += gridDim.x) {
        int m0 = tile * 128;

        float acc[MT][NT][4];
#pragma unroll
        for (int mt = 0; mt < MT; mt++)
#pragma unroll
            for (int nt = 0; nt < NT; nt++)
#pragma unroll
                for (int j = 0; j < 4; j++) acc[mt][nt][j] = 0.0f;

#pragma unroll 1
        for (int c = 0; c < 2; c++) {
            const __half* srcA = (c == 0) ? x : g_agg;
            __syncthreads();
            for (int i = tid; i < 128 * 16; i += 256) {
                int r = i >> 4;
                int k8 = (i & 15) << 3;
                int m = m0 + r;
                uint4 v = make_uint4(0, 0, 0, 0);
                if (m < N_NODES) v = *(const uint4*)&srcA[(long)m * 128 + k8];
                *(uint4*)&sA[r * KS_A + k8] = v;
            }
            __syncthreads();

#pragma unroll
            for (int kk = 0; kk < 128; kk += 16) {
                uint32_t a[MT][4];
#pragma unroll
                for (int mt = 0; mt < MT; mt++) {
                    uint32_t off = (uint32_t)((warpM + mt * 16 + rA) * KS_A + kk + kA) * 2;
                    ldsm_x4(a[mt][0], a[mt][1], a[mt][2], a[mt][3], uA + off);
                }
                uint32_t b[NT][2];
#pragma unroll
                for (int p = 0; p < NP; p++) {
                    uint32_t off =
                        (uint32_t)((warpN + p * 16 + rB4) * KS_B + c * 128 + kk + kB4) * 2;
                    ldsm_x4(b[2 * p][0], b[2 * p][1], b[2 * p + 1][0], b[2 * p + 1][1], uB + off);
                }
#pragma unroll
                for (int mt = 0; mt < MT; mt++)
#pragma unroll
                    for (int nt = 0; nt < NT; nt++) mma_f16(acc[mt][nt], a[mt], b[nt]);
            }
        }

#pragma unroll
        for (int mt = 0; mt < MT; mt++) {
#pragma unroll
            for (int nt = 0; nt < NT; nt++) {
                int n = warpN + nt * 8 + qc;
                float bn0 = sbias[n], bn1 = sbias[n + 1];
#pragma unroll
                for (int half = 0; half < 2; half++) {
                    int m = m0 + warpM + mt * 16 + qr + half * 8;
                    if (m >= N_NODES) continue;
                    float v0 = acc[mt][nt][half * 2 + 0] + bn0;
                    float v1 = acc[mt][nt][half * 2 + 1] + bn1;
                    if (RELU) { v0 = fmaxf(v0, 0.0f); v1 = fmaxf(v1, 0.0f); }
                    if (WF16) {
                        __half2 hv = __floats2half2_rn(v0, v1);
                        *(uint32_t*)&o_h[(long)m * 128 + n] = *(uint32_t*)&hv;
                    }
                    if (WF32) {
                        if (NOUT == 128) {
                            *(float2*)&out[(long)m * ostride + n] = make_float2(v0, v1);
                        } else {
                            if (n < N_CLS) out[(long)m * ostride + n] = v0;
                            if (n + 1 < N_CLS) out[(long)m * ostride + n + 1] = v1;
                        }
                    }
                }
            }
        }
    }
}

// ---------------- PDL launch helper ----------------
template <typename K, typename... Args>
static void launch_pdl(K kernel, dim3 grid, dim3 block, size_t smem, cudaStream_t stream,
                       Args... args) {
    cudaLaunchConfig_t cfg = {};
    cfg.gridDim = grid;
    cfg.blockDim = block;
    cfg.dynamicSmemBytes = smem;
    cfg.stream = stream;
    cudaLaunchAttribute at[1];
    at[0].id = cudaLaunchAttributeProgrammaticStreamSerialization;
    at[0].val.programmaticStreamSerializationAllowed = 1;
    cfg.attrs = at;
    cfg.numAttrs = 1;
    cudaLaunchKernelEx(&cfg, kernel, args...);
}

// ---------------- launch ----------------
extern "C" void kernel_launch(void* const* d_in, const int* in_sizes, int n_in,
                              void* d_out, int out_size) {
    const float* features = (const float*)d_in[0];
    const int*   src      = (const int*)d_in[1];
    const int*   dst      = (const int*)d_in[2];
    const float* Ws0 = (const float*)d_in[3];
    const float* Wn0 = (const float*)d_in[4];
    const float* b0  = (const float*)d_in[5];
    const float* Ws1 = (const float*)d_in[6];
    const float* Wn1 = (const float*)d_in[7];
    const float* b1  = (const float*)d_in[8];
    const float* Ws2 = (const float*)d_in[9];
    const float* Wn2 = (const float*)d_in[10];
    const float* b2  = (const float*)d_in[11];
    float* out = (float*)d_out;

    void* p;
    cudaGetSymbolAddress(&p, g_f);   __half* f = (__half*)p;
    cudaGetSymbolAddress(&p, g_h1);  __half* h1 = (__half*)p;
    cudaGetSymbolAddress(&p, g_h2);  __half* h2 = (__half*)p;
    cudaGetSymbolAddress(&p, g_B0);  __half* B0 = (__half*)p;
    cudaGetSymbolAddress(&p, g_B1);  __half* B1 = (__half*)p;
    cudaGetSymbolAddress(&p, g_B2);  __half* B2 = (__half*)p;

    const int SMEM128 = (128 * 264 + 128 * 136) * 2 + 512;  // 102,912
    const int SMEM48  = (48 * 264 + 128 * 136) * 2 + 512;   //  60,672
    cudaFuncSetAttribute(gemm_mma<128, true, true, false>,
                         cudaFuncAttributeMaxDynamicSharedMemorySize, SMEM128);
    cudaFuncSetAttribute(gemm_mma<48, false, false, true>,
                         cudaFuncAttributeMaxDynamicSharedMemorySize, SMEM48);

    // Fork: CSR chain on main stream, fused weight-prep + feature-convert on s2.
    cudaStream_t s2;
    cudaStreamCreateWithFlags(&s2, cudaStreamNonBlocking);
    cudaEvent_t e_fork, e_join;
    cudaEventCreateWithFlags(&e_fork, cudaEventDisableTiming);
    cudaEventCreateWithFlags(&e_join, cudaEventDisableTiming);

    cudaEventRecord(e_fork, 0);
    cudaStreamWaitEvent(s2, e_fork, 0);

    // s2: fused prep + convert (one kernel)
    prep_convert_kernel<<<CONV_BLOCKS + 128 + 128 + 48, 256, 0, s2>>>(
        features, f, Ws0, Wn0, Ws1, Wn1, Ws2, Wn2);
    cudaEventRecord(e_join, s2);

    // main: CSR build with PDL chaining (count -> scan -> fill)
    const int EDGE2_BLOCKS = ((N_EDGES + 1) / 2 + 255) / 256;
    count_rank_kernel<<<EDGE2_BLOCKS, 256>>>(dst);
    launch_pdl(scan_fused_kernel, SCAN_BLOCKS, SCAN_CHUNK, 0, (cudaStream_t)0);
    launch_pdl(fill_csr_kernel, EDGE2_BLOCKS, 256, 0, (cudaStream_t)0, src, dst);

    cudaStreamWaitEvent(0, e_join, 0);

    const int AGG_BLOCKS = (N_NODES * 32 + 255) / 256;
    const int NTILES = (N_NODES + 127) / 128;  // 391
    const int GEMM_GRID = 296;                 // 2 CTAs/SM persistent

    // Layer chain with PDL overlap at each boundary
    launch_pdl(agg_kernel, AGG_BLOCKS, 256, 0, (cudaStream_t)0, f);
    launch_pdl(gemm_mma<128, true, true, false>, GEMM_GRID, 256, SMEM128, (cudaStream_t)0,
               (const __half*)f, (const __half*)B0, b0, 128, (float*)nullptr, 128,
               (__half*)h1, NTILES);

    launch_pdl(agg_kernel, AGG_BLOCKS, 256, 0, (cudaStream_t)0, (const __half*)h1);
    launch_pdl(gemm_mma<128, true, true, false>, GEMM_GRID, 256, SMEM128, (cudaStream_t)0,
               (const __half*)h1, (const __half*)B1, b1, 128, (float*)nullptr, 128,
               (__half*)h2, NTILES);

    launch_pdl(agg_kernel, AGG_BLOCKS, 256, 0, (cudaStream_t)0, (const __half*)h2);
    launch_pdl(gemm_mma<48, false, false, true>, GEMM_GRID, 256, SMEM48, (cudaStream_t)0,
               (const __half*)h2, (const __half*)B2, b2, 47, out, 47,
               (__half*)nullptr, NTILES);
}